// round 14
// baseline (speedup 1.0000x reference)
#include <cuda_runtime.h>
#include <cuda_bf16.h>
#include <stdint.h>
#include <math.h>

#define BATCH   8
#define CDIM    512
#define HD      64
#define UNITS   512
#define PLANE_ALL ((size_t)BATCH * CDIM * 64 * 64)

// ---- bf16 hi/lo scratch in operand layouts ----
__device__ __nv_bfloat16 g_qh[(size_t)UNITS * 32768];
__device__ __nv_bfloat16 g_ql[(size_t)UNITS * 32768];
__device__ __nv_bfloat16 g_kh[(size_t)UNITS * 32768];
__device__ __nv_bfloat16 g_kl[(size_t)UNITS * 32768];
__device__ __nv_bfloat16 g_vh[(size_t)UNITS * 32768];
__device__ __nv_bfloat16 g_vl[(size_t)UNITS * 32768];
// S scratch, FRAGMENT-LINEAR: [cta][MT 4][CT 64][lane 32] x float4
__device__ float g_S[(size_t)4096 * 32768];
// per-row 1/L1 scale: [cta][64]
__device__ float g_ri[(size_t)4096 * 64];

#define BST 72      /* bf16 row stride (144B) */

// ---- attn1 smem ----
#define A1_QH    0
#define A1_QL    9216
#define A1_B0    18432      /* K chunk hi+lo = 18432; double buffer */
#define A1_PHI   55296      /* 512 f32 */
#define A1_SUM2  57344      /* 256 f32 */
#define SMEM_A1  58368

// ---- attn2 smem ----
#define A2_B0    0          /* V chunk (128 cols): 64 x 272B x2 = 34816; double */
#define A2_RI    69632      /* 64 f32 */
#define SMEM_A2  69888

__device__ __forceinline__ void split1(float x, __nv_bfloat16& h, __nv_bfloat16& l) {
    h = __float2bfloat16(x);
    l = __float2bfloat16(x - __bfloat162float(h));
}
__device__ __forceinline__ uint32_t packbf(__nv_bfloat16 a, __nv_bfloat16 c) {
    return (uint32_t)__bfloat16_as_ushort(a) | ((uint32_t)__bfloat16_as_ushort(c) << 16);
}
__device__ __forceinline__ uint32_t smem_u32(const void* p) {
    uint32_t a;
    asm("{ .reg .u64 t; cvta.to.shared.u64 t, %1; cvt.u32.u64 %0, t; }" : "=r"(a) : "l"(p));
    return a;
}
__device__ __forceinline__ void mma16816(float* c, uint32_t a0, uint32_t a1,
                                         uint32_t a2, uint32_t a3,
                                         uint32_t b0, uint32_t b1) {
    asm volatile(
        "mma.sync.aligned.m16n8k16.row.col.f32.bf16.bf16.f32 "
        "{%0,%1,%2,%3}, {%4,%5,%6,%7}, {%8,%9}, {%0,%1,%2,%3};"
        : "+f"(c[0]), "+f"(c[1]), "+f"(c[2]), "+f"(c[3])
        : "r"(a0), "r"(a1), "r"(a2), "r"(a3), "r"(b0), "r"(b1));
}
__device__ __forceinline__ void ldsm_x4(uint32_t& r0, uint32_t& r1, uint32_t& r2,
                                        uint32_t& r3, uint32_t addr) {
    asm volatile("ldmatrix.sync.aligned.m8n8.x4.shared.b16 {%0,%1,%2,%3}, [%4];"
                 : "=r"(r0), "=r"(r1), "=r"(r2), "=r"(r3) : "r"(addr));
}
#define CP16(d, s)  asm volatile("cp.async.cg.shared.global [%0], [%1], 16;" :: "r"(d), "l"(s))
#define CPCOMMIT()  asm volatile("cp.async.commit_group;" ::: "memory")
#define CPWAIT1()   asm volatile("cp.async.wait_group 1;" ::: "memory")
#define CPWAIT0()   asm volatile("cp.async.wait_group 0;" ::: "memory")

__device__ __forceinline__ float act1(float s, float ri) {
    const float K1 =  0.5f;
    const float K2 = -1.f / 24.f;
    const float K3 =  1.f / 720.f;
    const float K4 = -1.f / 40320.f;
    const float K5 =  1.f / 3628800.f;
    const float K6 = -1.f / 479001600.f;
    float x = s * ri;
    float z = x * x;
    float p = fmaf(z, K6, K5);
    p = fmaf(z, p, K4);
    p = fmaf(z, p, K3);
    p = fmaf(z, p, K2);
    p = fmaf(z, p, K1);
    return z * p;
}

// ---------------------------------------------------------------------------
// Pre-pass 1: Q (scaled) and K -> bf16 hi/lo scratch [unit][token][d]
// ---------------------------------------------------------------------------
__global__ __launch_bounds__(256)
void prep_qk(const float* __restrict__ temp) {
    __shared__ __nv_bfloat16 sh[64 * BST];
    __shared__ __nv_bfloat16 sl[64 * BST];
    int bid = blockIdx.x;
    int tsel = bid & 1, jc = (bid >> 1) & 7, unit = bid >> 4;
    int h = unit & 7, ww = (unit >> 3) & 7, b = unit >> 6;
    const float* src = temp + (size_t)tsel * PLANE_ALL + ((size_t)b * CDIM + h * HD) * 4096;
    float scale = tsel ? 1.f : 0.125f;

    int t = threadIdx.x, lane = t & 31, w = t >> 5;
    int j = w * 8 + (lane & 7);
    int jg = jc * 64 + j;
    int sp = (jg >> 3) * 64 + ww * 8 + (jg & 7);
    const float* col = src + sp;

    #pragma unroll
    for (int it = 0; it < 8; it++) {
        int d = (it * 4 + (lane >> 3)) * 2;
        float a = scale * col[(size_t)d * 4096];
        float c = scale * col[(size_t)(d + 1) * 4096];
        __nv_bfloat16 ah, al, ch, cl;
        split1(a, ah, al); split1(c, ch, cl);
        *(uint32_t*)((char*)sh + j * 144 + d * 2) = packbf(ah, ch);
        *(uint32_t*)((char*)sl + j * 144 + d * 2) = packbf(al, cl);
    }
    __syncthreads();

    __nv_bfloat16* dh = (tsel ? g_kh : g_qh) + (size_t)unit * 32768 + jc * 4096;
    __nv_bfloat16* dl = (tsel ? g_kl : g_ql) + (size_t)unit * 32768 + jc * 4096;
    int seg = lane & 7, r4 = lane >> 3;
    #pragma unroll
    for (int it = 0; it < 2; it++) {
        int r = w * 8 + it * 4 + r4;
        *(uint4*)((char*)(dh + r * 64) + seg * 16) = *(uint4*)((char*)sh + r * 144 + seg * 16);
        *(uint4*)((char*)(dl + r * 64) + seg * 16) = *(uint4*)((char*)sl + r * 144 + seg * 16);
    }
}

// ---------------------------------------------------------------------------
// Pre-pass 2: V -> bf16 hi/lo scratch [unit][d][j]
// ---------------------------------------------------------------------------
__global__ __launch_bounds__(256)
void prep_v(const float* __restrict__ temp) {
    int bid = blockIdx.x;
    int unit = bid >> 2, d0 = (bid & 3) * 16;
    int h = unit & 7, ww = (unit >> 3) & 7, b = unit >> 6;
    const float* vb = temp + 2 * PLANE_ALL + ((size_t)b * CDIM + h * HD) * 4096;
    int t = threadIdx.x;
    #pragma unroll
    for (int it = 0; it < 16; it++) {
        int pid = it * 256 + t;
        int j = (pid & 255) * 2;
        int d = d0 + (pid >> 8);
        int sp = (j >> 3) * 64 + ww * 8 + (j & 7);
        float2 x = *(const float2*)&vb[(size_t)d * 4096 + sp];
        __nv_bfloat16 ah, al, ch, cl;
        split1(x.x, ah, al); split1(x.y, ch, cl);
        size_t o = (size_t)unit * 32768 + d * 512 + j;
        *(uint32_t*)&g_vh[o] = packbf(ah, ch);
        *(uint32_t*)&g_vl[o] = packbf(al, cl);
    }
}

// ---------------------------------------------------------------------------
// Kernel A: depthwise 3x3 conv (lepe) -> writes base output layer
// ---------------------------------------------------------------------------
__global__ __launch_bounds__(256)
void lepe_kernel(const float* __restrict__ v, const float* __restrict__ cw,
                 const float* __restrict__ cb, float* __restrict__ out) {
    extern __shared__ float sm[];
    float* vs = sm;
    float* ws = vs + 64 * 195;
    float* bs = ws + 576;

    int bx = blockIdx.x;
    int b = bx >> 6, row = bx & 63;
    int c0 = blockIdx.y * 64;
    int t = threadIdx.x;

    for (int idx = t; idx < 64 * 3 * 64; idx += 256) {
        int c = idx / 192, rem = idx - c * 192;
        int r = rem >> 6, col = rem & 63;
        int gr = row + r - 1;
        float val = 0.f;
        if (gr >= 0 && gr < 64)
            val = v[(((size_t)b * CDIM + c0 + c) * 64 + gr) * 64 + col];
        vs[c * 195 + r * 65 + col] = val;
    }
    for (int idx = t; idx < 576; idx += 256) ws[idx] = cw[(size_t)c0 * 9 + idx];
    if (t < 64) bs[t] = cb[c0 + t];
    __syncthreads();

    int c = t & 63, cg = t >> 6;
    float w0 = ws[c*9+0], w1 = ws[c*9+1], w2 = ws[c*9+2];
    float w3 = ws[c*9+3], w4 = ws[c*9+4], w5 = ws[c*9+5];
    float w6 = ws[c*9+6], w7 = ws[c*9+7], w8 = ws[c*9+8];
    float bias = bs[c];
    const float* base = &vs[c * 195];

    #pragma unroll
    for (int it = 0; it < 16; it++) {
        int col = it * 4 + cg;
        float l0 = (col > 0)  ? base[0*65 + col - 1] : 0.f;
        float l1 = (col > 0)  ? base[1*65 + col - 1] : 0.f;
        float l2 = (col > 0)  ? base[2*65 + col - 1] : 0.f;
        float m0 = base[0*65 + col], m1 = base[1*65 + col], m2 = base[2*65 + col];
        float r0 = (col < 63) ? base[0*65 + col + 1] : 0.f;
        float r1 = (col < 63) ? base[1*65 + col + 1] : 0.f;
        float r2 = (col < 63) ? base[2*65 + col + 1] : 0.f;
        float sum = bias;
        sum += l0*w0 + m0*w1 + r0*w2;
        sum += l1*w3 + m1*w4 + r1*w5;
        sum += l2*w6 + m2*w7 + r2*w8;
        out[((size_t)b * 4096 + row * 64 + col) * CDIM + c0 + c] = sum;
    }
}

// ---------------------------------------------------------------------------
// attn1: S = Qs @ K^T + rpe -> g_S (fragment-linear); row L1 -> g_ri.
// 2m x 4n roles; QH frags cached, QL + K streamed. 3 CTAs/SM.
// ---------------------------------------------------------------------------
__global__ __launch_bounds__(256, 3)
void attn1_kernel(const float* __restrict__ polar) {
    extern __shared__ char smc[];
    const uint32_t sb = smem_u32(smc);
    float* phiA = (float*)(smc + A1_PHI);
    float* sum2 = (float*)(smc + A1_SUM2);

    int t = threadIdx.x;
    int bid = blockIdx.x;
    int rb = bid & 7;
    int unit = bid >> 3;
    int ww = (unit >> 3) & 7, b = unit >> 6;

    int lane = t & 31, wid = t >> 5;
    int g = lane >> 2, tg = lane & 3;
    int mg = wid >> 2, nq = wid & 3;

    float4* Sg4 = (float4*)(g_S + (size_t)bid * 32768);

    int lrow = lane & 7, lsel = lane >> 3;
    uint32_t b_off1 = (uint32_t)((nq * 16 + lrow) * 144 + lsel * 16);
    uint32_t a_offm[2];
    #pragma unroll
    for (int mt = 0; mt < 2; mt++)
        a_offm[mt] = (uint32_t)((mg * 32 + mt * 16 + (lsel & 1) * 8 + lrow) * 144
                                + (lsel >> 1) * 16);

    const __nv_bfloat16* qh = g_qh + (size_t)unit * 32768 + rb * 4096;
    const __nv_bfloat16* ql = g_ql + (size_t)unit * 32768 + rb * 4096;
    const __nv_bfloat16* kh = g_kh + (size_t)unit * 32768;
    const __nv_bfloat16* kl = g_kl + (size_t)unit * 32768;

    int crow = t >> 3, cseg = t & 7;
    #define CPY64R(dstoff, srcp) do {                                           \
        _Pragma("unroll")                                                       \
        for (int k_ = 0; k_ < 2; k_++) {                                        \
            int row_ = crow + k_ * 32;                                          \
            CP16(sb + (dstoff) + row_ * 144 + cseg * 16,                        \
                 (const char*)((srcp) + (size_t)row_ * 64) + cseg * 16);        \
        }                                                                       \
    } while (0)

    // prologue: G0 = Q + K0, G1 = K1
    CPY64R(A1_QH, qh);
    CPY64R(A1_QL, ql);
    CPY64R(A1_B0, kh);
    CPY64R(A1_B0 + 9216, kl);
    CPCOMMIT();

    for (int s = t; s < 512; s += 256) {
        int rp = s >> 3, cp = ww * 8 + (s & 7);
        phiA[s] = polar[(((size_t)b * 64 + rp) * 64 + cp) * 2 + 1];
    }

    CPY64R(A1_B0 + 18432, kh + 4096);
    CPY64R(A1_B0 + 18432 + 9216, kl + 4096);
    CPCOMMIT();

    CPWAIT1();
    __syncthreads();

    // QH fragments cached (32 regs)
    uint32_t aqh[2][4][4];
    #pragma unroll
    for (int mt = 0; mt < 2; mt++)
        #pragma unroll
        for (int kt = 0; kt < 4; kt++)
            ldsm_x4(aqh[mt][kt][0], aqh[mt][kt][1], aqh[mt][kt][2], aqh[mt][kt][3],
                    sb + A1_QH + a_offm[mt] + kt * 32);

    float phq0[2], phq1[2];
    #pragma unroll
    for (int mt = 0; mt < 2; mt++) {
        phq0[mt] = phiA[rb * 64 + mg * 32 + mt * 16 + g];
        phq1[mt] = phiA[rb * 64 + mg * 32 + mt * 16 + g + 8];
    }
    float rs[4] = {0.f, 0.f, 0.f, 0.f};

    for (int jc = 0; jc < 8; jc++) {
        uint32_t kbase = sb + A1_B0 + (uint32_t)(jc & 1) * 18432;

        float acc[2][2][4];
        #pragma unroll
        for (int mt = 0; mt < 2; mt++)
            #pragma unroll
            for (int nt = 0; nt < 2; nt++)
                #pragma unroll
                for (int e = 0; e < 4; e++) acc[mt][nt][e] = 0.f;

        // term 0: QH x KH (KH streamed per kt2)
        #pragma unroll
        for (int kt2 = 0; kt2 < 2; kt2++)
            #pragma unroll
            for (int nt = 0; nt < 2; nt++) {
                uint32_t b0, b1, b2, b3;
                ldsm_x4(b0, b1, b2, b3, kbase + b_off1 + nt * 1152 + kt2 * 64);
                #pragma unroll
                for (int mt = 0; mt < 2; mt++) {
                    mma16816(acc[mt][nt], aqh[mt][2*kt2][0], aqh[mt][2*kt2][1],
                             aqh[mt][2*kt2][2], aqh[mt][2*kt2][3], b0, b1);
                    mma16816(acc[mt][nt], aqh[mt][2*kt2+1][0], aqh[mt][2*kt2+1][1],
                             aqh[mt][2*kt2+1][2], aqh[mt][2*kt2+1][3], b2, b3);
                }
            }
        // term 1: QH x KL (KL streamed)
        #pragma unroll
        for (int kt2 = 0; kt2 < 2; kt2++)
            #pragma unroll
            for (int nt = 0; nt < 2; nt++) {
                uint32_t b0, b1, b2, b3;
                ldsm_x4(b0, b1, b2, b3, kbase + 9216 + b_off1 + nt * 1152 + kt2 * 64);
                #pragma unroll
                for (int mt = 0; mt < 2; mt++) {
                    mma16816(acc[mt][nt], aqh[mt][2*kt2][0], aqh[mt][2*kt2][1],
                             aqh[mt][2*kt2][2], aqh[mt][2*kt2][3], b0, b1);
                    mma16816(acc[mt][nt], aqh[mt][2*kt2+1][0], aqh[mt][2*kt2+1][1],
                             aqh[mt][2*kt2+1][2], aqh[mt][2*kt2+1][3], b2, b3);
                }
            }
        // term 2: QL (streamed) x KH (reloaded)
        #pragma unroll
        for (int kt2 = 0; kt2 < 2; kt2++) {
            uint32_t bk[2][4];
            #pragma unroll
            for (int nt = 0; nt < 2; nt++)
                ldsm_x4(bk[nt][0], bk[nt][1], bk[nt][2], bk[nt][3],
                        kbase + b_off1 + nt * 1152 + kt2 * 64);
            #pragma unroll
            for (int mt = 0; mt < 2; mt++) {
                uint32_t a0[4], a1[4];
                ldsm_x4(a0[0], a0[1], a0[2], a0[3],
                        sb + A1_QL + a_offm[mt] + (2*kt2) * 32);
                ldsm_x4(a1[0], a1[1], a1[2], a1[3],
                        sb + A1_QL + a_offm[mt] + (2*kt2+1) * 32);
                #pragma unroll
                for (int nt = 0; nt < 2; nt++) {
                    mma16816(acc[mt][nt], a0[0], a0[1], a0[2], a0[3], bk[nt][0], bk[nt][1]);
                    mma16816(acc[mt][nt], a1[0], a1[1], a1[2], a1[3], bk[nt][2], bk[nt][3]);
                }
            }
        }

        // fold rpe, L1 partials, store fragment-linear
        #pragma unroll
        for (int mt = 0; mt < 2; mt++)
            #pragma unroll
            for (int nt = 0; nt < 2; nt++) {
                int colj = jc * 64 + nq * 16 + nt * 8 + tg * 2;
                float2 pk = *(const float2*)&phiA[colj];
                float s0 = acc[mt][nt][0] + phq0[mt] - pk.x;
                float s1 = acc[mt][nt][1] + phq0[mt] - pk.y;
                float s2 = acc[mt][nt][2] + phq1[mt] - pk.x;
                float s3 = acc[mt][nt][3] + phq1[mt] - pk.y;
                rs[mt * 2 + 0] += fabsf(s0) + fabsf(s1);
                rs[mt * 2 + 1] += fabsf(s2) + fabsf(s3);
                int MT = mg * 2 + mt;
                int CT = jc * 8 + nq * 2 + nt;
                Sg4[(MT * 64 + CT) * 32 + lane] = make_float4(s0, s1, s2, s3);
            }

        __syncthreads();                          // chunk jc consumed
        if (jc < 6) {
            uint32_t bo = A1_B0 + (uint32_t)(jc & 1) * 18432;
            CPY64R(bo, kh + (jc + 2) * 4096);
            CPY64R(bo + 9216, kl + (jc + 2) * 4096);
            CPCOMMIT();
        }
        if (jc < 7) {
            if (jc < 6) { CPWAIT1(); } else { CPWAIT0(); }
            __syncthreads();
        }
    }

    // ---- row L1 -> g_ri ----
    #pragma unroll
    for (int i = 0; i < 4; i++) {
        rs[i] += __shfl_xor_sync(0xffffffffu, rs[i], 1);
        rs[i] += __shfl_xor_sync(0xffffffffu, rs[i], 2);
    }
    if (tg == 0) {
        #pragma unroll
        for (int mt = 0; mt < 2; mt++) {
            int r0 = mg * 32 + mt * 16 + g;
            sum2[r0 * 4 + nq]       = rs[mt * 2 + 0];
            sum2[(r0 + 8) * 4 + nq] = rs[mt * 2 + 1];
        }
    }
    __syncthreads();
    if (t < 64)
        g_ri[(size_t)bid * 64 + t] = 1.5707963267948966f /
            (sum2[t*4] + sum2[t*4+1] + sum2[t*4+2] + sum2[t*4+3] + 1e-8f);
}

// ---------------------------------------------------------------------------
// attn2: P = act(S*ri); O = P @ V^T; RMW into out. 4m x 2n roles.
// P frags rebuilt from fragment-linear g_S in registers. 3 CTAs/SM.
// ---------------------------------------------------------------------------
__global__ __launch_bounds__(256, 3)
void attn2_kernel(float* __restrict__ out) {
    extern __shared__ char smc[];
    const uint32_t sb = smem_u32(smc);
    float* riA = (float*)(smc + A2_RI);

    int t = threadIdx.x;
    int bid = blockIdx.x;
    int rb = bid & 7;
    int unit = bid >> 3;
    int ww = (unit >> 3) & 7, b = unit >> 6;

    int lane = t & 31, wid = t >> 5;
    int g = lane >> 2, tg = lane & 3;
    int mt2 = wid >> 1;
    int nb = (wid & 1) * 32;

    float4* Sg4 = (float4*)(g_S + (size_t)bid * 32768);

    int lrow = lane & 7, lsel = lane >> 3;
    uint32_t b_off2 = (uint32_t)((nb + lrow) * 272 + lsel * 16);

    const __nv_bfloat16* vh = g_vh + (size_t)unit * 32768;
    const __nv_bfloat16* vl = g_vl + (size_t)unit * 32768;

    int vrow = t >> 4, vseg = t & 15;
    #define CPYV2(dstoff, srcp) do {                                            \
        _Pragma("unroll")                                                       \
        for (int k_ = 0; k_ < 4; k_++) {                                        \
            int row_ = vrow + k_ * 16;                                          \
            CP16(sb + (dstoff) + row_ * 272 + vseg * 16,                        \
                 (const char*)((srcp) + (size_t)row_ * 512) + vseg * 16);       \
        }                                                                       \
    } while (0)

    // prologue: G0 = V0, G1 = V1
    CPYV2(A2_B0, vh);
    CPYV2(A2_B0 + 17408, vl);
    CPCOMMIT();
    CPYV2(A2_B0 + 34816, vh + 128);
    CPYV2(A2_B0 + 34816 + 17408, vl + 128);
    CPCOMMIT();

    if (t < 64) riA[t] = g_ri[(size_t)bid * 64 + t];

    CPWAIT1();
    __syncthreads();

    float ri_a = riA[mt2 * 16 + g];
    float ri_b = riA[mt2 * 16 + g + 8];

    float oacc[4][4];
    #pragma unroll
    for (int nt = 0; nt < 4; nt++)
        #pragma unroll
        for (int e = 0; e < 4; e++) oacc[nt][e] = 0.f;

    for (int jc = 0; jc < 4; jc++) {
        uint32_t vbase = sb + A2_B0 + (uint32_t)(jc & 1) * 34816;

        #pragma unroll
        for (int kh2 = 0; kh2 < 2; kh2++) {
            // build P A-frags in registers from fragment-linear S
            uint32_t aph[4][4], apl[4][4];
            #pragma unroll
            for (int kt = 0; kt < 4; kt++) {
                int CT = jc * 16 + kh2 * 8 + 2 * kt;
                float4 u = Sg4[(mt2 * 64 + CT) * 32 + lane];
                float4 w = Sg4[(mt2 * 64 + CT + 1) * 32 + lane];
                float p0 = act1(u.x, ri_a), p1 = act1(u.y, ri_a);
                float p2 = act1(u.z, ri_b), p3 = act1(u.w, ri_b);
                float p4 = act1(w.x, ri_a), p5 = act1(w.y, ri_a);
                float p6 = act1(w.z, ri_b), p7 = act1(w.w, ri_b);
                __nv_bfloat16 h0,l0,h1,l1,h2,l2,h3,l3,h4,l4,h5,l5,h6,l6,h7,l7;
                split1(p0,h0,l0); split1(p1,h1,l1); split1(p2,h2,l2); split1(p3,h3,l3);
                split1(p4,h4,l4); split1(p5,h5,l5); split1(p6,h6,l6); split1(p7,h7,l7);
                aph[kt][0] = packbf(h0,h1); apl[kt][0] = packbf(l0,l1);
                aph[kt][1] = packbf(h2,h3); apl[kt][1] = packbf(l2,l3);
                aph[kt][2] = packbf(h4,h5); apl[kt][2] = packbf(l4,l5);
                aph[kt][3] = packbf(h6,h7); apl[kt][3] = packbf(l6,l7);
            }

            uint32_t koffB = (uint32_t)kh2 * 128;

            // term 0: PH x VH (VH streamed)
            #pragma unroll
            for (int kt2 = 0; kt2 < 2; kt2++)
                #pragma unroll
                for (int nt = 0; nt < 4; nt++) {
                    uint32_t b0, b1, b2, b3;
                    ldsm_x4(b0, b1, b2, b3,
                            vbase + b_off2 + koffB + nt * 2176 + kt2 * 64);
                    mma16816(oacc[nt], aph[2*kt2][0], aph[2*kt2][1], aph[2*kt2][2], aph[2*kt2][3], b0, b1);
                    mma16816(oacc[nt], aph[2*kt2+1][0], aph[2*kt2+1][1], aph[2*kt2+1][2], aph[2*kt2+1][3], b2, b3);
                }
            // term 1: PH x VL (VL streamed)
            #pragma unroll
            for (int kt2 = 0; kt2 < 2; kt2++)
                #pragma unroll
                for (int nt = 0; nt < 4; nt++) {
                    uint32_t b0, b1, b2, b3;
                    ldsm_x4(b0, b1, b2, b3,
                            vbase + 17408 + b_off2 + koffB + nt * 2176 + kt2 * 64);
                    mma16816(oacc[nt], aph[2*kt2][0], aph[2*kt2][1], aph[2*kt2][2], aph[2*kt2][3], b0, b1);
                    mma16816(oacc[nt], aph[2*kt2+1][0], aph[2*kt2+1][1], aph[2*kt2+1][2], aph[2*kt2+1][3], b2, b3);
                }
            // term 2: PL x VH (VH reloaded)
            #pragma unroll
            for (int kt2 = 0; kt2 < 2; kt2++)
                #pragma unroll
                for (int nt = 0; nt < 4; nt++) {
                    uint32_t b0, b1, b2, b3;
                    ldsm_x4(b0, b1, b2, b3,
                            vbase + b_off2 + koffB + nt * 2176 + kt2 * 64);
                    mma16816(oacc[nt], apl[2*kt2][0], apl[2*kt2][1], apl[2*kt2][2], apl[2*kt2][3], b0, b1);
                    mma16816(oacc[nt], apl[2*kt2+1][0], apl[2*kt2+1][1], apl[2*kt2+1][2], apl[2*kt2+1][3], b2, b3);
                }
        }

        __syncthreads();                          // buf consumed
        if (jc < 2) {
            uint32_t bo = A2_B0 + (uint32_t)(jc & 1) * 34816;
            CPYV2(bo, vh + (jc + 2) * 128);
            CPYV2(bo + 17408, vl + (jc + 2) * 128);
            CPCOMMIT();
        }
        if (jc < 3) {
            if (jc < 2) { CPWAIT1(); } else { CPWAIT0(); }
            __syncthreads();
        }
    }

    // ---- Epilogue: RMW into out (lepe base already written) ----
    {
        int h = unit & 7;
        int sg0 = rb * 64 + mt2 * 16 + g;
        int sg1 = sg0 + 8;
        int sp0 = (sg0 >> 3) * 64 + ww * 8 + (sg0 & 7);
        int sp1 = (sg1 >> 3) * 64 + ww * 8 + (sg1 & 7);
        float* o0 = out + ((size_t)b * 4096 + sp0) * CDIM + h * HD;
        float* o1 = out + ((size_t)b * 4096 + sp1) * CDIM + h * HD;
        #pragma unroll
        for (int nt = 0; nt < 4; nt++) {
            int d0 = nb + nt * 8 + tg * 2;
            float2 c0 = *(float2*)&o0[d0];
            c0.x += oacc[nt][0]; c0.y += oacc[nt][1];
            *(float2*)&o0[d0] = c0;
            float2 c1 = *(float2*)&o1[d0];
            c1.x += oacc[nt][2]; c1.y += oacc[nt][3];
            *(float2*)&o1[d0] = c1;
        }
    }
}

// ---------------------------------------------------------------------------
extern "C" void kernel_launch(void* const* d_in, const int* in_sizes, int n_in,
                              void* d_out, int out_size) {
    const float* temp  = (const float*)d_in[0];  // [3, 8, 512, 64, 64]
    const float* polar = (const float*)d_in[1];  // [8, 64, 64, 2]
    const float* cw    = (const float*)d_in[2];  // [512, 1, 3, 3]
    const float* cb    = (const float*)d_in[3];  // [512]
    float* out = (float*)d_out;                  // [8, 4096, 512]

    const float* v = temp + 2 * PLANE_ALL;

    size_t smA = (size_t)(64 * 195 + 576 + 64) * sizeof(float);
    cudaFuncSetAttribute(lepe_kernel, cudaFuncAttributeMaxDynamicSharedMemorySize, (int)smA);
    cudaFuncSetAttribute(attn1_kernel, cudaFuncAttributeMaxDynamicSharedMemorySize, SMEM_A1);
    cudaFuncSetAttribute(attn2_kernel, cudaFuncAttributeMaxDynamicSharedMemorySize, SMEM_A2);

    prep_qk<<<UNITS * 16, 256>>>(temp);
    prep_v<<<UNITS * 4, 256>>>(temp);

    dim3 gA(BATCH * 64, CDIM / 64);
    lepe_kernel<<<gA, 256, smA>>>(v, cw, cb, out);
    attn1_kernel<<<4096, 256, SMEM_A1>>>(polar);
    attn2_kernel<<<4096, 256, SMEM_A2>>>(out);
}

// round 17
// speedup vs baseline: 1.1955x; 1.1955x over previous
#include <cuda_runtime.h>
#include <cuda_bf16.h>
#include <stdint.h>
#include <math.h>

#define BATCH   8
#define CDIM    512
#define HD      64
#define UNITS   512
#define PLANE_ALL ((size_t)BATCH * CDIM * 64 * 64)

// ---- bf16 hi/lo scratch in operand layouts ----
__device__ __nv_bfloat16 g_qh[(size_t)UNITS * 32768];
__device__ __nv_bfloat16 g_ql[(size_t)UNITS * 32768];
__device__ __nv_bfloat16 g_kh[(size_t)UNITS * 32768];
__device__ __nv_bfloat16 g_kl[(size_t)UNITS * 32768];
__device__ __nv_bfloat16 g_vh[(size_t)UNITS * 32768];
__device__ __nv_bfloat16 g_vl[(size_t)UNITS * 32768];
// S scratch, FRAGMENT-LINEAR: [cta][MT 4][CT 64][lane 32] x float4
__device__ float g_S[(size_t)4096 * 32768];

#define BST 72      /* bf16 row stride (144B) */

// ---- attn smem (57.3 KB -> 3 CTAs/SM) ----
#define OFF_QH   0
#define OFF_QL   9216
#define OFF_B0   18432     /* K/V chunk hi+lo = 18432; double buffer */
#define OFF_PHI  55296     /* 512 f32 */
#define OFF_RI   57344     /* 64 f32 */
#define OFF_SUM2 57600     /* 256 f32 */
#define SMEM_ATTN 58624

__device__ __forceinline__ void split1(float x, __nv_bfloat16& h, __nv_bfloat16& l) {
    h = __float2bfloat16(x);
    l = __float2bfloat16(x - __bfloat162float(h));
}
__device__ __forceinline__ uint32_t packbf(__nv_bfloat16 a, __nv_bfloat16 c) {
    return (uint32_t)__bfloat16_as_ushort(a) | ((uint32_t)__bfloat16_as_ushort(c) << 16);
}
__device__ __forceinline__ uint32_t smem_u32(const void* p) {
    uint32_t a;
    asm("{ .reg .u64 t; cvta.to.shared.u64 t, %1; cvt.u32.u64 %0, t; }" : "=r"(a) : "l"(p));
    return a;
}
__device__ __forceinline__ void mma16816(float* c, uint32_t a0, uint32_t a1,
                                         uint32_t a2, uint32_t a3,
                                         uint32_t b0, uint32_t b1) {
    asm volatile(
        "mma.sync.aligned.m16n8k16.row.col.f32.bf16.bf16.f32 "
        "{%0,%1,%2,%3}, {%4,%5,%6,%7}, {%8,%9}, {%0,%1,%2,%3};"
        : "+f"(c[0]), "+f"(c[1]), "+f"(c[2]), "+f"(c[3])
        : "r"(a0), "r"(a1), "r"(a2), "r"(a3), "r"(b0), "r"(b1));
}
__device__ __forceinline__ void ldsm_x4(uint32_t& r0, uint32_t& r1, uint32_t& r2,
                                        uint32_t& r3, uint32_t addr) {
    asm volatile("ldmatrix.sync.aligned.m8n8.x4.shared.b16 {%0,%1,%2,%3}, [%4];"
                 : "=r"(r0), "=r"(r1), "=r"(r2), "=r"(r3) : "r"(addr));
}
#define CP16(d, s)  asm volatile("cp.async.cg.shared.global [%0], [%1], 16;" :: "r"(d), "l"(s))
#define CPCOMMIT()  asm volatile("cp.async.commit_group;" ::: "memory")
#define CPWAIT1()   asm volatile("cp.async.wait_group 1;" ::: "memory")
#define CPWAIT0()   asm volatile("cp.async.wait_group 0;" ::: "memory")

__device__ __forceinline__ float act1(float s, float ri) {
    const float K1 =  0.5f;
    const float K2 = -1.f / 24.f;
    const float K3 =  1.f / 720.f;
    const float K4 = -1.f / 40320.f;
    const float K5 =  1.f / 3628800.f;
    const float K6 = -1.f / 479001600.f;
    float x = s * ri;
    float z = x * x;
    float p = fmaf(z, K6, K5);
    p = fmaf(z, p, K4);
    p = fmaf(z, p, K3);
    p = fmaf(z, p, K2);
    p = fmaf(z, p, K1);
    return z * p;
}

// ---------------------------------------------------------------------------
// Pre-pass 1: Q (scaled) and K -> bf16 hi/lo scratch [unit][token][d]
// ---------------------------------------------------------------------------
__global__ __launch_bounds__(256)
void prep_qk(const float* __restrict__ temp) {
    __shared__ __nv_bfloat16 sh[64 * BST];
    __shared__ __nv_bfloat16 sl[64 * BST];
    int bid = blockIdx.x;
    int tsel = bid & 1, jc = (bid >> 1) & 7, unit = bid >> 4;
    int h = unit & 7, ww = (unit >> 3) & 7, b = unit >> 6;
    const float* src = temp + (size_t)tsel * PLANE_ALL + ((size_t)b * CDIM + h * HD) * 4096;
    float scale = tsel ? 1.f : 0.125f;

    int t = threadIdx.x, lane = t & 31, w = t >> 5;
    int j = w * 8 + (lane & 7);
    int jg = jc * 64 + j;
    int sp = (jg >> 3) * 64 + ww * 8 + (jg & 7);
    const float* col = src + sp;

    #pragma unroll
    for (int it = 0; it < 8; it++) {
        int d = (it * 4 + (lane >> 3)) * 2;
        float a = scale * col[(size_t)d * 4096];
        float c = scale * col[(size_t)(d + 1) * 4096];
        __nv_bfloat16 ah, al, ch, cl;
        split1(a, ah, al); split1(c, ch, cl);
        *(uint32_t*)((char*)sh + j * 144 + d * 2) = packbf(ah, ch);
        *(uint32_t*)((char*)sl + j * 144 + d * 2) = packbf(al, cl);
    }
    __syncthreads();

    __nv_bfloat16* dh = (tsel ? g_kh : g_qh) + (size_t)unit * 32768 + jc * 4096;
    __nv_bfloat16* dl = (tsel ? g_kl : g_ql) + (size_t)unit * 32768 + jc * 4096;
    int seg = lane & 7, r4 = lane >> 3;
    #pragma unroll
    for (int it = 0; it < 2; it++) {
        int r = w * 8 + it * 4 + r4;
        *(uint4*)((char*)(dh + r * 64) + seg * 16) = *(uint4*)((char*)sh + r * 144 + seg * 16);
        *(uint4*)((char*)(dl + r * 64) + seg * 16) = *(uint4*)((char*)sl + r * 144 + seg * 16);
    }
}

// ---------------------------------------------------------------------------
// Pre-pass 2: V -> bf16 hi/lo scratch [unit][d][j]
// ---------------------------------------------------------------------------
__global__ __launch_bounds__(256)
void prep_v(const float* __restrict__ temp) {
    int bid = blockIdx.x;
    int unit = bid >> 2, d0 = (bid & 3) * 16;
    int h = unit & 7, ww = (unit >> 3) & 7, b = unit >> 6;
    const float* vb = temp + 2 * PLANE_ALL + ((size_t)b * CDIM + h * HD) * 4096;
    int t = threadIdx.x;
    #pragma unroll
    for (int it = 0; it < 16; it++) {
        int pid = it * 256 + t;
        int j = (pid & 255) * 2;
        int d = d0 + (pid >> 8);
        int sp = (j >> 3) * 64 + ww * 8 + (j & 7);
        float2 x = *(const float2*)&vb[(size_t)d * 4096 + sp];
        __nv_bfloat16 ah, al, ch, cl;
        split1(x.x, ah, al); split1(x.y, ch, cl);
        size_t o = (size_t)unit * 32768 + d * 512 + j;
        *(uint32_t*)&g_vh[o] = packbf(ah, ch);
        *(uint32_t*)&g_vl[o] = packbf(al, cl);
    }
}

// ---------------------------------------------------------------------------
// Kernel A: depthwise 3x3 conv (lepe) -> writes base output layer
// ---------------------------------------------------------------------------
__global__ __launch_bounds__(256)
void lepe_kernel(const float* __restrict__ v, const float* __restrict__ cw,
                 const float* __restrict__ cb, float* __restrict__ out) {
    extern __shared__ float sm[];
    float* vs = sm;
    float* ws = vs + 64 * 195;
    float* bs = ws + 576;

    int bx = blockIdx.x;
    int b = bx >> 6, row = bx & 63;
    int c0 = blockIdx.y * 64;
    int t = threadIdx.x;

    for (int idx = t; idx < 64 * 3 * 64; idx += 256) {
        int c = idx / 192, rem = idx - c * 192;
        int r = rem >> 6, col = rem & 63;
        int gr = row + r - 1;
        float val = 0.f;
        if (gr >= 0 && gr < 64)
            val = v[(((size_t)b * CDIM + c0 + c) * 64 + gr) * 64 + col];
        vs[c * 195 + r * 65 + col] = val;
    }
    for (int idx = t; idx < 576; idx += 256) ws[idx] = cw[(size_t)c0 * 9 + idx];
    if (t < 64) bs[t] = cb[c0 + t];
    __syncthreads();

    int c = t & 63, cg = t >> 6;
    float w0 = ws[c*9+0], w1 = ws[c*9+1], w2 = ws[c*9+2];
    float w3 = ws[c*9+3], w4 = ws[c*9+4], w5 = ws[c*9+5];
    float w6 = ws[c*9+6], w7 = ws[c*9+7], w8 = ws[c*9+8];
    float bias = bs[c];
    const float* base = &vs[c * 195];

    #pragma unroll
    for (int it = 0; it < 16; it++) {
        int col = it * 4 + cg;
        float l0 = (col > 0)  ? base[0*65 + col - 1] : 0.f;
        float l1 = (col > 0)  ? base[1*65 + col - 1] : 0.f;
        float l2 = (col > 0)  ? base[2*65 + col - 1] : 0.f;
        float m0 = base[0*65 + col], m1 = base[1*65 + col], m2 = base[2*65 + col];
        float r0 = (col < 63) ? base[0*65 + col + 1] : 0.f;
        float r1 = (col < 63) ? base[1*65 + col + 1] : 0.f;
        float r2 = (col < 63) ? base[2*65 + col + 1] : 0.f;
        float sum = bias;
        sum += l0*w0 + m0*w1 + r0*w2;
        sum += l1*w3 + m1*w4 + r1*w5;
        sum += l2*w6 + m2*w7 + r2*w8;
        out[((size_t)b * 4096 + row * 64 + col) * CDIM + c0 + c] = sum;
    }
}

// ---------------------------------------------------------------------------
// Kernel B: monolithic attention at 3 CTAs/SM (register-lean phases).
// Phase1: 2m x 4n, QH cached / QL+K streamed -> g_S fragment-linear (L2-hot).
// Phase2: 4m x 2n, P frags rebuilt in registers, V streamed.
// grid 4096, 256 threads.
// ---------------------------------------------------------------------------
__global__ __launch_bounds__(256, 3)
void attn_mma_kernel(const float* __restrict__ polar, float* __restrict__ out) {
    extern __shared__ char smc[];
    const uint32_t sb = smem_u32(smc);
    float* phiA = (float*)(smc + OFF_PHI);
    float* riA  = (float*)(smc + OFF_RI);
    float* sum2 = (float*)(smc + OFF_SUM2);

    int t = threadIdx.x;
    int bid = blockIdx.x;
    int rb = bid & 7;
    int unit = bid >> 3;
    int ww = (unit >> 3) & 7, b = unit >> 6;

    int lane = t & 31, wid = t >> 5;
    int g = lane >> 2, tg = lane & 3;
    int mg = wid >> 2, nq = wid & 3;       // phase-1 roles
    int mt2 = wid >> 1;                    // phase-2 / epilogue roles
    int nb = (wid & 1) * 32;

    float4* Sg4 = (float4*)(g_S + (size_t)bid * 32768);

    int lrow = lane & 7, lsel = lane >> 3;
    uint32_t b_off1 = (uint32_t)((nq * 16 + lrow) * 144 + lsel * 16);   // phase1 B
    uint32_t b_off2 = (uint32_t)((nb + lrow) * 144 + lsel * 16);        // phase2 B
    uint32_t a_offm[2];
    #pragma unroll
    for (int mt = 0; mt < 2; mt++)
        a_offm[mt] = (uint32_t)((mg * 32 + mt * 16 + (lsel & 1) * 8 + lrow) * 144
                                + (lsel >> 1) * 16);

    const __nv_bfloat16* qh = g_qh + (size_t)unit * 32768 + rb * 4096;
    const __nv_bfloat16* ql = g_ql + (size_t)unit * 32768 + rb * 4096;
    const __nv_bfloat16* kh = g_kh + (size_t)unit * 32768;
    const __nv_bfloat16* kl = g_kl + (size_t)unit * 32768;
    const __nv_bfloat16* vh = g_vh + (size_t)unit * 32768;
    const __nv_bfloat16* vl = g_vl + (size_t)unit * 32768;

    int crow = t >> 3, cseg = t & 7;
    // 64 rows x 128B copy into 144B-stride smem
    #define CPY64(dstoff, srcp, rstride) do {                                   \
        _Pragma("unroll")                                                       \
        for (int k_ = 0; k_ < 2; k_++) {                                        \
            int row_ = crow + k_ * 32;                                          \
            CP16(sb + (dstoff) + row_ * 144 + cseg * 16,                        \
                 (const char*)((srcp) + (size_t)row_ * (rstride)) + cseg * 16); \
        }                                                                       \
    } while (0)

    // prologue: G0 = Q + K0, G1 = K1
    CPY64(OFF_QH, qh, 64);
    CPY64(OFF_QL, ql, 64);
    CPY64(OFF_B0, kh, 64);
    CPY64(OFF_B0 + 9216, kl, 64);
    CPCOMMIT();

    for (int s = t; s < 512; s += 256) {
        int rp = s >> 3, cp = ww * 8 + (s & 7);
        phiA[s] = polar[(((size_t)b * 64 + rp) * 64 + cp) * 2 + 1];
    }

    CPY64(OFF_B0 + 18432, kh + 4096, 64);
    CPY64(OFF_B0 + 18432 + 9216, kl + 4096, 64);
    CPCOMMIT();

    CPWAIT1();
    __syncthreads();

    // ---- QH fragments cached (32 regs) ----
    uint32_t aqh[2][4][4];
    #pragma unroll
    for (int mt = 0; mt < 2; mt++)
        #pragma unroll
        for (int kt = 0; kt < 4; kt++)
            ldsm_x4(aqh[mt][kt][0], aqh[mt][kt][1], aqh[mt][kt][2], aqh[mt][kt][3],
                    sb + OFF_QH + a_offm[mt] + kt * 32);

    float phq0[2], phq1[2];
    #pragma unroll
    for (int mt = 0; mt < 2; mt++) {
        phq0[mt] = phiA[rb * 64 + mg * 32 + mt * 16 + g];
        phq1[mt] = phiA[rb * 64 + mg * 32 + mt * 16 + g + 8];
    }
    float rs[4] = {0.f, 0.f, 0.f, 0.f};

    // ---- Phase 1: S = Qs @ K^T + rpe -> fragment-linear g_S ----
    for (int jc = 0; jc < 8; jc++) {
        uint32_t kbase = sb + OFF_B0 + (uint32_t)(jc & 1) * 18432;

        float acc[2][2][4];
        #pragma unroll
        for (int mt = 0; mt < 2; mt++)
            #pragma unroll
            for (int nt = 0; nt < 2; nt++)
                #pragma unroll
                for (int e = 0; e < 4; e++) acc[mt][nt][e] = 0.f;

        // term 0: QH x KH (KH streamed)
        #pragma unroll
        for (int kt2 = 0; kt2 < 2; kt2++)
            #pragma unroll
            for (int nt = 0; nt < 2; nt++) {
                uint32_t b0, b1, b2, b3;
                ldsm_x4(b0, b1, b2, b3, kbase + b_off1 + nt * 1152 + kt2 * 64);
                #pragma unroll
                for (int mt = 0; mt < 2; mt++) {
                    mma16816(acc[mt][nt], aqh[mt][2*kt2][0], aqh[mt][2*kt2][1],
                             aqh[mt][2*kt2][2], aqh[mt][2*kt2][3], b0, b1);
                    mma16816(acc[mt][nt], aqh[mt][2*kt2+1][0], aqh[mt][2*kt2+1][1],
                             aqh[mt][2*kt2+1][2], aqh[mt][2*kt2+1][3], b2, b3);
                }
            }
        // term 1: QH x KL (KL streamed)
        #pragma unroll
        for (int kt2 = 0; kt2 < 2; kt2++)
            #pragma unroll
            for (int nt = 0; nt < 2; nt++) {
                uint32_t b0, b1, b2, b3;
                ldsm_x4(b0, b1, b2, b3, kbase + 9216 + b_off1 + nt * 1152 + kt2 * 64);
                #pragma unroll
                for (int mt = 0; mt < 2; mt++) {
                    mma16816(acc[mt][nt], aqh[mt][2*kt2][0], aqh[mt][2*kt2][1],
                             aqh[mt][2*kt2][2], aqh[mt][2*kt2][3], b0, b1);
                    mma16816(acc[mt][nt], aqh[mt][2*kt2+1][0], aqh[mt][2*kt2+1][1],
                             aqh[mt][2*kt2+1][2], aqh[mt][2*kt2+1][3], b2, b3);
                }
            }
        // term 2: QL (streamed) x KH (reloaded)
        #pragma unroll
        for (int kt2 = 0; kt2 < 2; kt2++) {
            uint32_t bk[2][4];
            #pragma unroll
            for (int nt = 0; nt < 2; nt++)
                ldsm_x4(bk[nt][0], bk[nt][1], bk[nt][2], bk[nt][3],
                        kbase + b_off1 + nt * 1152 + kt2 * 64);
            #pragma unroll
            for (int mt = 0; mt < 2; mt++) {
                uint32_t a0[4], a1[4];
                ldsm_x4(a0[0], a0[1], a0[2], a0[3],
                        sb + OFF_QL + a_offm[mt] + (2*kt2) * 32);
                ldsm_x4(a1[0], a1[1], a1[2], a1[3],
                        sb + OFF_QL + a_offm[mt] + (2*kt2+1) * 32);
                #pragma unroll
                for (int nt = 0; nt < 2; nt++) {
                    mma16816(acc[mt][nt], a0[0], a0[1], a0[2], a0[3], bk[nt][0], bk[nt][1]);
                    mma16816(acc[mt][nt], a1[0], a1[1], a1[2], a1[3], bk[nt][2], bk[nt][3]);
                }
            }
        }

        // fold rpe, L1 partials, store fragment-linear
        #pragma unroll
        for (int mt = 0; mt < 2; mt++)
            #pragma unroll
            for (int nt = 0; nt < 2; nt++) {
                int colj = jc * 64 + nq * 16 + nt * 8 + tg * 2;
                float2 pk = *(const float2*)&phiA[colj];
                float s0 = acc[mt][nt][0] + phq0[mt] - pk.x;
                float s1 = acc[mt][nt][1] + phq0[mt] - pk.y;
                float s2 = acc[mt][nt][2] + phq1[mt] - pk.x;
                float s3 = acc[mt][nt][3] + phq1[mt] - pk.y;
                rs[mt * 2 + 0] += fabsf(s0) + fabsf(s1);
                rs[mt * 2 + 1] += fabsf(s2) + fabsf(s3);
                int MT = mg * 2 + mt;
                int CT = jc * 8 + nq * 2 + nt;
                Sg4[(MT * 64 + CT) * 32 + lane] = make_float4(s0, s1, s2, s3);
            }

        __syncthreads();                          // chunk jc consumed
        if (jc < 6) {
            uint32_t bo = OFF_B0 + (uint32_t)(jc & 1) * 18432;
            CPY64(bo, kh + (jc + 2) * 4096, 64);
            CPY64(bo + 9216, kl + (jc + 2) * 4096, 64);
            CPCOMMIT();
        } else if (jc == 6) {                     // prefetch V chunk0 into buf0
            CPY64(OFF_B0, vh, 512);
            CPY64(OFF_B0 + 9216, vl, 512);
            CPCOMMIT();
        }
        if (jc < 7) {
            CPWAIT1();
            __syncthreads();
        }
    }

    // ---- row L1 -> ri ----
    #pragma unroll
    for (int i = 0; i < 4; i++) {
        rs[i] += __shfl_xor_sync(0xffffffffu, rs[i], 1);
        rs[i] += __shfl_xor_sync(0xffffffffu, rs[i], 2);
    }
    if (tg == 0) {
        #pragma unroll
        for (int mt = 0; mt < 2; mt++) {
            int r0 = mg * 32 + mt * 16 + g;
            sum2[r0 * 4 + nq]       = rs[mt * 2 + 0];
            sum2[(r0 + 8) * 4 + nq] = rs[mt * 2 + 1];
        }
    }
    __syncthreads();
    if (t < 64)
        riA[t] = 1.5707963267948966f /
                 (sum2[t*4] + sum2[t*4+1] + sum2[t*4+2] + sum2[t*4+3] + 1e-8f);
    __syncthreads();

    // ---- Phase 2: P = act(S*ri); O += P @ V^T ----
    float oacc[4][4];
    #pragma unroll
    for (int nt = 0; nt < 4; nt++)
        #pragma unroll
        for (int e = 0; e < 4; e++) oacc[nt][e] = 0.f;

    float ri_a = riA[mt2 * 16 + g];
    float ri_b = riA[mt2 * 16 + g + 8];

    for (int jc = 0; jc < 8; jc++) {
        if (jc < 7) {
            uint32_t bo = OFF_B0 + (uint32_t)((jc + 1) & 1) * 18432;
            CPY64(bo, vh + (jc + 1) * 64, 512);
            CPY64(bo + 9216, vl + (jc + 1) * 64, 512);
            CPCOMMIT();
        }
        // build P A-frags in registers from fragment-linear S (overlaps copy)
        uint32_t aph[4][4], apl[4][4];
        #pragma unroll
        for (int kt = 0; kt < 4; kt++) {
            int CT = jc * 8 + 2 * kt;
            float4 u = Sg4[(mt2 * 64 + CT) * 32 + lane];
            float4 w = Sg4[(mt2 * 64 + CT + 1) * 32 + lane];
            float p0 = act1(u.x, ri_a), p1 = act1(u.y, ri_a);
            float p2 = act1(u.z, ri_b), p3 = act1(u.w, ri_b);
            float p4 = act1(w.x, ri_a), p5 = act1(w.y, ri_a);
            float p6 = act1(w.z, ri_b), p7 = act1(w.w, ri_b);
            __nv_bfloat16 h0,l0,h1,l1,h2,l2,h3,l3,h4,l4,h5,l5,h6,l6,h7,l7;
            split1(p0,h0,l0); split1(p1,h1,l1); split1(p2,h2,l2); split1(p3,h3,l3);
            split1(p4,h4,l4); split1(p5,h5,l5); split1(p6,h6,l6); split1(p7,h7,l7);
            aph[kt][0] = packbf(h0,h1); apl[kt][0] = packbf(l0,l1);
            aph[kt][1] = packbf(h2,h3); apl[kt][1] = packbf(l2,l3);
            aph[kt][2] = packbf(h4,h5); apl[kt][2] = packbf(l4,l5);
            aph[kt][3] = packbf(h6,h7); apl[kt][3] = packbf(l6,l7);
        }
        if (jc < 7) { CPWAIT1(); } else { CPWAIT0(); }
        __syncthreads();                          // V chunk jc ready

        uint32_t vbase = sb + OFF_B0 + (uint32_t)(jc & 1) * 18432;

        // term 0: PH x VH (VH streamed)
        #pragma unroll
        for (int kt2 = 0; kt2 < 2; kt2++)
            #pragma unroll
            for (int nt = 0; nt < 4; nt++) {
                uint32_t b0, b1, b2, b3;
                ldsm_x4(b0, b1, b2, b3, vbase + b_off2 + nt * 1152 + kt2 * 64);
                mma16816(oacc[nt], aph[2*kt2][0], aph[2*kt2][1], aph[2*kt2][2], aph[2*kt2][3], b0, b1);
                mma16816(oacc[nt], aph[2*kt2+1][0], aph[2*kt2+1][1], aph[2*kt2+1][2], aph[2*kt2+1][3], b2, b3);
            }
        // term 1: PH x VL (VL streamed)
        #pragma unroll
        for (int kt2 = 0; kt2 < 2; kt2++)
            #pragma unroll
            for (int nt = 0; nt < 4; nt++) {
                uint32_t b0, b1, b2, b3;
                ldsm_x4(b0, b1, b2, b3, vbase + 9216 + b_off2 + nt * 1152 + kt2 * 64);
                mma16816(oacc[nt], aph[2*kt2][0], aph[2*kt2][1], aph[2*kt2][2], aph[2*kt2][3], b0, b1);
                mma16816(oacc[nt], aph[2*kt2+1][0], aph[2*kt2+1][1], aph[2*kt2+1][2], aph[2*kt2+1][3], b2, b3);
            }
        // term 2: PL x VH (VH reloaded)
        #pragma unroll
        for (int kt2 = 0; kt2 < 2; kt2++)
            #pragma unroll
            for (int nt = 0; nt < 4; nt++) {
                uint32_t b0, b1, b2, b3;
                ldsm_x4(b0, b1, b2, b3, vbase + b_off2 + nt * 1152 + kt2 * 64);
                mma16816(oacc[nt], apl[2*kt2][0], apl[2*kt2][1], apl[2*kt2][2], apl[2*kt2][3], b0, b1);
                mma16816(oacc[nt], apl[2*kt2+1][0], apl[2*kt2+1][1], apl[2*kt2+1][2], apl[2*kt2+1][3], b2, b3);
            }

        __syncthreads();                          // before next V overwrite
    }

    // ---- Epilogue: RMW into out (lepe base already written) ----
    {
        int h = unit & 7;
        int sg0 = rb * 64 + mt2 * 16 + g;
        int sg1 = sg0 + 8;
        int sp0 = (sg0 >> 3) * 64 + ww * 8 + (sg0 & 7);
        int sp1 = (sg1 >> 3) * 64 + ww * 8 + (sg1 & 7);
        float* o0 = out + ((size_t)b * 4096 + sp0) * CDIM + h * HD;
        float* o1 = out + ((size_t)b * 4096 + sp1) * CDIM + h * HD;
        #pragma unroll
        for (int nt = 0; nt < 4; nt++) {
            int d0 = nb + nt * 8 + tg * 2;
            float2 c0 = *(float2*)&o0[d0];
            c0.x += oacc[nt][0]; c0.y += oacc[nt][1];
            *(float2*)&o0[d0] = c0;
            float2 c1 = *(float2*)&o1[d0];
            c1.x += oacc[nt][2]; c1.y += oacc[nt][3];
            *(float2*)&o1[d0] = c1;
        }
    }
}

// ---------------------------------------------------------------------------
extern "C" void kernel_launch(void* const* d_in, const int* in_sizes, int n_in,
                              void* d_out, int out_size) {
    const float* temp  = (const float*)d_in[0];  // [3, 8, 512, 64, 64]
    const float* polar = (const float*)d_in[1];  // [8, 64, 64, 2]
    const float* cw    = (const float*)d_in[2];  // [512, 1, 3, 3]
    const float* cb    = (const float*)d_in[3];  // [512]
    float* out = (float*)d_out;                  // [8, 4096, 512]

    const float* v = temp + 2 * PLANE_ALL;

    size_t smA = (size_t)(64 * 195 + 576 + 64) * sizeof(float);
    cudaFuncSetAttribute(lepe_kernel, cudaFuncAttributeMaxDynamicSharedMemorySize, (int)smA);
    cudaFuncSetAttribute(attn_mma_kernel, cudaFuncAttributeMaxDynamicSharedMemorySize, SMEM_ATTN);

    prep_qk<<<UNITS * 16, 256>>>(temp);
    prep_v<<<UNITS * 4, 256>>>(temp);

    dim3 gA(BATCH * 64, CDIM / 64);
    lepe_kernel<<<gA, 256, smA>>>(v, cw, cb, out);
    attn_mma_kernel<<<4096, 256, SMEM_ATTN>>>(polar, out);
}